// round 3
// baseline (speedup 1.0000x reference)
#include <cuda_runtime.h>

#define HH   4096
#define WW   4096
#define ROWF (WW*3)          // 12288 floats per image row
#define BW   128             // columns per block
#define TPB  384             // one thread per (col, chan)
#define CH   256             // output rows per block
#define WARM 44              // IIR warm-up rows (decay^44 ~ 2.7e-10)
#define RAD  3               // blur radius (tail <= 1.2e-8 of weight)
#define STAGE_F 408          // (BW + 2*4)*3 halo-4 stage, 16B aligned
#define NVEC 102             // STAGE_F / 4

// sigma=0.5 Gaussian taps normalized over the full 25-tap window (= reference)
#define K0f 0.78657070f
#define K1f 0.10645078f
#define K2f 2.63866e-4f
#define K3f 1.19790e-8f
#define DECAYf 0.60653065971263342f
#define OMDf   0.39346934028736658f
#define INV3f  0.33333322222f        // 1/(3 + 1e-6)

__global__ __launch_bounds__(TPB, 3)
void chem_kernel(const float* __restrict__ D, const float* __restrict__ Cm,
                 float* __restrict__ out)
{
    const int tid = threadIdx.x;
    const int c   = tid % 3;
    const int w0  = blockIdx.x * BW;
    const int h0  = blockIdx.y * CH;

    __shared__ float4 st4[NVEC];     // row stage (halo 4 cols each side)
    __shared__ float  shI[TPB];      // inhibitor exchange for channel mix

    float* stg = (float*)st4;

    // ---- cooperative vectorized loader mapping (tid < 102) ----
    const bool ldr   = tid < NVEC;
    const int  gbase = (w0 - 4) * 3 + 4 * tid;          // row-relative float idx
    // edge blocks: OOB halo regions are exact float4 multiples -> full-vec predicate
    const bool gok   = ldr && (gbase >= 0) && (gbase + 4 <= ROWF);

    // coupling column for this thread's output channel j=c: inh_j = sum_i C[i][j]*x_i
    const float cc0 = __ldg(Cm + 0 + c);
    const float cc1 = __ldg(Cm + 3 + c);
    const float cc2 = __ldg(Cm + 6 + c);

    // per-thread register rings (vertical blur / d / soft), static-indexed via unroll-8
    float hb[8]  = {0,0,0,0,0,0,0,0};
    float dr_[4] = {0,0,0,0};
    float sr_[4] = {0,0,0,0};
    float siir = 0.f;

    int r = h0 - WARM;                                   // row committed this body
    const float* rp = D + (size_t)r * ROWF;
    float* op = out + (size_t)(r - RAD) * ROWF + w0 * 3 + tid;

    // 2-deep ping-pong prefetch
    float4 pf0 = make_float4(0,0,0,0), pf1 = make_float4(0,0,0,0);
    if (gok && r     >= 0 && r     < HH) pf0 = *(const float4*)(rp + gbase);
    if (gok && r + 1 >= 0 && r + 1 < HH) pf1 = *(const float4*)(rp + ROWF + gbase);

#define BODY(S) { \
    /* commit prefetched row r into the stage, immediately refill slot with row r+2 */ \
    if (ldr) { \
        st4[tid] = ((S)&1) ? pf1 : pf0; \
        float4 nv = make_float4(0,0,0,0); \
        const int rn = r + 2; \
        if (gok && rn >= 0 && rn < HH) nv = *(const float4*)(rp + 2*ROWF + gbase); \
        if ((S)&1) pf1 = nv; else pf0 = nv; \
    } \
    __syncthreads();  /* A: stage ready */ \
    { \
        const int si = tid + 3; \
        const float xm3 = stg[si],    xm2 = stg[si+3],  xm1 = stg[si+6]; \
        const float x0  = stg[si+9]; \
        const float xp1 = stg[si+12], xp2 = stg[si+15], xp3 = stg[si+18]; \
        float hbv = x0 * K0f; \
        hbv += (xm1 + xp1) * K1f; \
        hbv += (xm2 + xp2) * K2f; \
        hbv += (xm3 + xp3) * K3f; \
        siir = x0 + DECAYf * siir; \
        hb[(S)&7]  = hbv; \
        dr_[(S)&3] = x0; \
        sr_[(S)&3] = OMDf * siir; \
        /* vertical blur for output row ro = r-3 : slots (S-j)&7 hold row r-j */ \
        float vb = hb[((S)+5)&7] * K0f; \
        vb += (hb[((S)+4)&7] + hb[((S)+6)&7]) * K1f; \
        vb += (hb[((S)+3)&7] + hb[((S)+7)&7]) * K2f; \
        vb += (hb[((S)+2)&7] + hb[(S)&7])     * K3f; \
        const float d_o = dr_[((S)+1)&3]; \
        const float s_o = sr_[((S)+1)&3]; \
        float m = fminf(fmaxf(d_o * INV3f, 0.f), 1.f); \
        shI[tid] = s_o + m * (vb - s_o); \
        __syncthreads();  /* B: inhibitor exchange ready */ \
        const int ro = r - RAD; \
        if (ro >= h0 && ro < h0 + CH) { \
            const int wb = tid - c; \
            const float i0 = shI[wb], i1 = shI[wb+1], i2 = shI[wb+2]; \
            const float inh = cc0*i0 + cc1*i1 + cc2*i2; \
            const float arg = (d_o - inh) * INV3f; \
            float t; asm("tanh.approx.f32 %0, %1;" : "=f"(t) : "f"(arg)); \
            *op = 3.0f * t; \
        } \
    } \
    ++r; rp += ROWF; op += ROWF; \
}

    // CH + WARM + RAD = 303 -> 38 * 8 = 304 bodies (tail body emits nothing)
#pragma unroll 1
    for (int ii = 0; ii < 38; ++ii) {
        BODY(0) BODY(1) BODY(2) BODY(3)
        BODY(4) BODY(5) BODY(6) BODY(7)
    }
#undef BODY
}

extern "C" void kernel_launch(void* const* d_in, const int* in_sizes, int n_in,
                              void* d_out, int out_size)
{
    const float* D   = (const float*)d_in[0];   // (4096, 4096, 3) f32
    const float* Cm  = (const float*)d_in[1];   // (3, 3) f32
    float*       out = (float*)d_out;           // (4096, 4096, 3) f32
    dim3 grid(WW / BW, HH / CH);                // 32 x 16 = 512 blocks
    chem_kernel<<<grid, TPB>>>(D, Cm, out);
}

// round 5
// speedup vs baseline: 3.0780x; 3.0780x over previous
#include <cuda_runtime.h>

#define HH 4096
#define WW 4096
#define ROWF 12288          // floats per image row
#define BW 128              // columns per block
#define TPB 384             // one thread per (col, chan)
#define CH 256              // output rows per block
#define WARM 44             // IIR warm-up rows (decay^44 ~ 2.7e-10)
#define RVEC 102            // float4 per staged row (128+8 halo cols)
#define RSTRIDE 408         // floats per staged row
#define BUFBYTES 6528       // 4 rows * 408 floats * 4B

typedef unsigned int u32;

// sigma=0.5 taps normalized over the full 25-tap window (= reference), radius 3
#define K0f 0.78657070f
#define K1f 0.10645078f
#define K2f 2.63866e-4f
#define K3f 1.19790e-8f
#define DECAYf 0.60653065971263342f
#define OMDf   0.39346934028736658f
#define INV3f  0.33333322222f        // 1/(3 + 1e-6)

__global__ __launch_bounds__(TPB, 4)
void chem_kernel(const float* __restrict__ D, const float* __restrict__ Cm,
                 float* __restrict__ out)
{
    __shared__ float4 stage[2][4][RVEC];   // 13056 B, double-buffered 4-row batch
    __shared__ float  shI[4][TPB];         // 6144 B inhibitor exchange

    const int tid = threadIdx.x;
    const int c   = tid % 3;
    const int wb_ = tid - c;
    const int w0  = blockIdx.x * BW;
    const int h0  = blockIdx.y * CH;

    const float cc0 = __ldg(Cm + 0 + c);
    const float cc1 = __ldg(Cm + 3 + c);
    const float cc2 = __ldg(Cm + 6 + c);

    // ---- cp.async loader mapping: vec v of 408 -> (row v/102, lane v%102) ----
    const int  j0     = tid / RVEC;                       // 0..3
    const int  v0     = tid - j0 * RVEC;
    const long goff0  = (long)(w0 - 4) * 3 + 4 * v0;      // row-relative float idx
    const bool colok0 = (goff0 >= 0) && (goff0 + 4 <= ROWF);
    const bool sec    = tid < 24;                         // vecs 384..407 (row 3)
    const long goff1  = (long)(w0 - 4) * 3 + 4 * (78 + tid);
    const bool colok1 = sec && (goff1 >= 0) && (goff1 + 4 <= ROWF);

    const u32 sb = (u32)__cvta_generic_to_shared(stage);
    const u32 sAddr0[2] = { sb + (u32)((j0 * RSTRIDE + 4 * v0) * 4),
                            sb + BUFBYTES + (u32)((j0 * RSTRIDE + 4 * v0) * 4) };
    const u32 sAddr1[2] = { sb + (u32)((3 * RSTRIDE + 4 * (78 + tid)) * 4),
                            sb + BUFBYTES + (u32)((3 * RSTRIDE + 4 * (78 + tid)) * 4) };

    float hb[8] = {0,0,0,0,0,0,0,0};   // horizontal-blur ring (static idx via phases)
    float dr[4] = {0,0,0,0};           // raw density ring (lag 3)
    float sr[4] = {0,0,0,0};           // soft-cloud ring (lag 3)
    float ds[4];                       // density stash for mix phase
    float siir = 0.f;

    int rb = h0 - WARM;                // base row of current batch

#define ISSUE(RB, BUF) { \
    const int  row = (RB) + j0; \
    const int  sz  = (colok0 && row >= 0 && row < HH) ? 16 : 0; \
    const float* g = sz ? (D + (long)row * ROWF + goff0) : D; \
    asm volatile("cp.async.cg.shared.global [%0], [%1], 16, %2;\n" \
                 :: "r"(sAddr0[BUF]), "l"(g), "r"(sz) : "memory"); \
    if (sec) { \
        const int  row1 = (RB) + 3; \
        const int  sz1  = (colok1 && row1 >= 0 && row1 < HH) ? 16 : 0; \
        const float* g1 = sz1 ? (D + (long)row1 * ROWF + goff1) : D; \
        asm volatile("cp.async.cg.shared.global [%0], [%1], 16, %2;\n" \
                     :: "r"(sAddr1[BUF]), "l"(g1), "r"(sz1) : "memory"); \
    } \
    asm volatile("cp.async.commit_group;\n" ::: "memory"); }

#define ROWCOMP(S, J, EMIT) { \
    const float* bp = stgf + (J) * RSTRIDE; \
    const float xm3 = bp[tid+3],  xm2 = bp[tid+6],  xm1 = bp[tid+9]; \
    const float x0  = bp[tid+12]; \
    const float xp1 = bp[tid+15], xp2 = bp[tid+18], xp3 = bp[tid+21]; \
    float hbv = x0 * K0f; \
    hbv = fmaf(xm1 + xp1, K1f, hbv); \
    hbv = fmaf(xm2 + xp2, K2f, hbv); \
    hbv = fmaf(xm3 + xp3, K3f, hbv); \
    siir = fmaf(DECAYf, siir, x0); \
    hb[(S)&7] = hbv; \
    if (EMIT) { \
        float vb = hb[((S)+5)&7] * K0f; \
        vb = fmaf(hb[((S)+4)&7] + hb[((S)+6)&7], K1f, vb); \
        vb = fmaf(hb[((S)+3)&7] + hb[((S)+7)&7], K2f, vb); \
        vb = fmaf(hb[((S)+2)&7] + hb[(S)&7],     K3f, vb); \
        const float d_o = dr[((S)+1)&3]; \
        const float s_o = sr[((S)+1)&3]; \
        float m = fminf(fmaxf(d_o * INV3f, 0.f), 1.f); \
        ds[J] = d_o; \
        shI[J][tid] = s_o + m * (vb - s_o); \
    } \
    dr[(S)&3] = x0; \
    sr[(S)&3] = OMDf * siir; }

#define MIX(J) { \
    const int ro = rb + (J) - 3; \
    if (ro >= h0 && ro < h0 + CH) { \
        const float i0 = shI[J][wb_], i1 = shI[J][wb_+1], i2 = shI[J][wb_+2]; \
        const float inh = cc0*i0 + cc1*i1 + cc2*i2; \
        const float arg = (ds[J] - inh) * INV3f; \
        float t; asm("tanh.approx.f32 %0, %1;" : "=f"(t) : "f"(arg)); \
        out[(size_t)ro * ROWF + w0*3 + tid] = 3.0f * t; \
    } }

#define CPWAIT(N) asm volatile("cp.async.wait_group " #N ";\n" ::: "memory")

#define SUPER(S0, BUF, EMIT, WAITN, ISS) { \
    CPWAIT(WAITN); \
    __syncthreads();                 /* A: batch rb visible everywhere */ \
    const float* stgf = (const float*)stage[BUF]; \
    ROWCOMP((S0)+0, 0, EMIT) ROWCOMP((S0)+1, 1, EMIT) \
    ROWCOMP((S0)+2, 2, EMIT) ROWCOMP((S0)+3, 3, EMIT) \
    __syncthreads();                 /* B: stage reads done, shI visible */ \
    if (ISS) ISSUE(rb + 8, BUF)      /* refill this buffer for batch b+2 */ \
    if (EMIT) { MIX(0) MIX(1) MIX(2) MIX(3) } \
    rb += 4; }

    // prologue: batches 0,1 in flight
    ISSUE(rb,     0)
    ISSUE(rb + 4, 1)

    // warm-up: batches 0..10 (no emission)
#pragma unroll 1
    for (int p = 0; p < 5; ++p) { SUPER(0, 0, 0, 1, 1) SUPER(4, 1, 0, 1, 1) }
    SUPER(0, 0, 0, 1, 1)            // b=10
    SUPER(4, 1, 1, 1, 1)            // b=11, first emission (row h0)

    // main: batches 12..73
#pragma unroll 1
    for (int p = 0; p < 31; ++p) { SUPER(0, 0, 1, 1, 1) SUPER(4, 1, 1, 1, 1) }

    // tail: batches 74,75 — no further issues; last waits all
    SUPER(0, 0, 1, 1, 0)            // b=74
    SUPER(4, 1, 1, 0, 0)            // b=75

#undef SUPER
#undef CPWAIT
#undef MIX
#undef ROWCOMP
#undef ISSUE
}

extern "C" void kernel_launch(void* const* d_in, const int* in_sizes, int n_in,
                              void* d_out, int out_size)
{
    const float* D   = (const float*)d_in[0];   // (4096, 4096, 3) f32
    const float* Cm  = (const float*)d_in[1];   // (3, 3) f32
    float*       out = (float*)d_out;           // (4096, 4096, 3) f32
    dim3 grid(WW / BW, HH / CH);                // 32 x 16 = 512 blocks
    chem_kernel<<<grid, TPB>>>(D, Cm, out);
}

// round 9
// speedup vs baseline: 3.8194x; 1.2408x over previous
#include <cuda_runtime.h>
typedef unsigned int u32;

#define HH 4096
#define ROWF 12288          // floats per image row
#define TPB 384             // one thread per (col, chan)
#define CH 256              // output rows per block
#define RVEC 102            // float4 per staged row (128 + 8 halo cols)
#define RSTRIDE 408         // floats per staged row
#define BUFBYTES 6528       // 4 rows * 408 floats * 4B

// sigma=0.5 taps normalized over the full 25-tap window (= reference), radius 2
#define K0f 0.78657070f
#define K1f 0.10645078f
#define K2f 2.63866e-4f
#define DECAYf 0.60653065971263342f
#define OMDf   0.39346934028736658f
#define INV3f  0.33333322222f        // 1/(3 + 1e-6)

__global__ __launch_bounds__(TPB, 4)
void chem_kernel(const float* __restrict__ D, const float* __restrict__ Cm,
                 float* __restrict__ out)
{
    __shared__ float4 stage[2][4][RVEC];   // 13056 B, double-buffered 4-row batch
    __shared__ float  shI[4][TPB];         // 6144 B inhibitor exchange

    const int tid = threadIdx.x;
    const int c   = tid % 3;
    const int wb_ = tid - c;
    const int w0  = blockIdx.x << 7;       // 32 strips of 128 cols
    const int h0  = blockIdx.y * CH;

    const float cc0 = __ldg(Cm + 0 + c);
    const float cc1 = __ldg(Cm + 3 + c);
    const float cc2 = __ldg(Cm + 6 + c);

    // ---- cp.async loader mapping: vec v of 408 -> (row v/102, lane v%102) ----
    const int  j0     = tid / RVEC;                       // 0..3
    const int  v0     = tid - j0 * RVEC;
    const long goff0  = (long)(w0 - 4) * 3 + 4 * v0;      // row-relative float idx
    const bool colok0 = (goff0 >= 0) && (goff0 + 4 <= ROWF);
    const bool sec    = tid < 24;                         // vecs 384..407 (row 3)
    const long goff1  = (long)(w0 - 4) * 3 + 4 * (78 + tid);
    const bool colok1 = sec && (goff1 >= 0) && (goff1 + 4 <= ROWF);

    const u32 sb = (u32)__cvta_generic_to_shared(stage);
    const u32 sAddr0[2] = { sb + (u32)((j0 * RSTRIDE + 4 * v0) * 4),
                            sb + BUFBYTES + (u32)((j0 * RSTRIDE + 4 * v0) * 4) };
    const u32 sAddr1[2] = { sb + (u32)((3 * RSTRIDE + 4 * (78 + tid)) * 4),
                            sb + BUFBYTES + (u32)((3 * RSTRIDE + 4 * (78 + tid)) * 4) };

    float hb[8] = {0,0,0,0,0,0,0,0};   // horizontal-blur ring (static idx via phases)
    float dr[4] = {0,0,0,0};           // raw density ring (lag 2)
    float sr[4] = {0,0,0,0};           // soft-cloud ring (lag 2)
    float ds[4];
    float siir = 0.f;

    int rb = h0 - 30;                  // 72 batches of 4; emit batches 8..71
    float* op = out + (long)(rb - 2) * ROWF + w0 * 3 + tid;

#define ISSUE(RB, BUF) { \
    const int  row = (RB) + j0; \
    const int  sz  = (colok0 && row >= 0 && row < HH) ? 16 : 0; \
    const float* g = sz ? (D + (long)row * ROWF + goff0) : D; \
    asm volatile("cp.async.cg.shared.global [%0], [%1], 16, %2;\n" \
                 :: "r"(sAddr0[BUF]), "l"(g), "r"(sz) : "memory"); \
    if (sec) { \
        const int  row1 = (RB) + 3; \
        const int  sz1  = (colok1 && row1 >= 0 && row1 < HH) ? 16 : 0; \
        const float* g1 = sz1 ? (D + (long)row1 * ROWF + goff1) : D; \
        asm volatile("cp.async.cg.shared.global [%0], [%1], 16, %2;\n" \
                     :: "r"(sAddr1[BUF]), "l"(g1), "r"(sz1) : "memory"); \
    } \
    asm volatile("cp.async.commit_group;\n" ::: "memory"); }

// Row r committed at phase S; output row ro = r-2. hb[(S-k)&7] holds row r-k.
#define ROWCOMP(S, J) { \
    const float* bp = stgf + (J) * RSTRIDE; \
    const float xm2 = bp[tid+6],  xm1 = bp[tid+9]; \
    const float x0  = bp[tid+12]; \
    const float xp1 = bp[tid+15], xp2 = bp[tid+18]; \
    float hbv = x0 * K0f; \
    hbv = fmaf(xm1 + xp1, K1f, hbv); \
    hbv = fmaf(xm2 + xp2, K2f, hbv); \
    siir = fmaf(DECAYf, siir, x0); \
    hb[(S)&7] = hbv; \
    float vb = hb[((S)+6)&7] * K0f; \
    vb = fmaf(hb[((S)+7)&7] + hb[((S)+5)&7], K1f, vb); \
    vb = fmaf(hb[(S)&7]     + hb[((S)+4)&7], K2f, vb); \
    const float d_o = dr[((S)+2)&3]; \
    const float s_o = sr[((S)+2)&3]; \
    ds[J] = d_o; \
    shI[J][tid] = s_o + (d_o * INV3f) * (vb - s_o); \
    dr[(S)&3] = x0; \
    sr[(S)&3] = OMDf * siir; }

#define MIX(J) { \
    const float i0 = shI[J][wb_], i1 = shI[J][wb_+1], i2 = shI[J][wb_+2]; \
    const float inh = cc0*i0 + cc1*i1 + cc2*i2; \
    const float arg = (ds[J] - inh) * INV3f; \
    float t; asm("tanh.approx.f32 %0, %1;" : "=f"(t) : "f"(arg)); \
    op[(J)*ROWF] = 3.0f * t; }

#define CPWAIT(N) asm volatile("cp.async.wait_group " #N ";\n" ::: "memory")

#define SUPER(S0, BUF, EMIT, WAITN, ISS) { \
    CPWAIT(WAITN); \
    __syncthreads();                 /* stage batch visible */ \
    const float* stgf = (const float*)stage[BUF]; \
    ROWCOMP((S0)+0, 0) ROWCOMP((S0)+1, 1) \
    ROWCOMP((S0)+2, 2) ROWCOMP((S0)+3, 3) \
    __syncthreads();                 /* stage reads done, shI visible */ \
    if (ISS) ISSUE(rb + 8, BUF)      /* refill this buffer for batch b+2 */ \
    if (EMIT) { MIX(0) MIX(1) MIX(2) MIX(3) } \
    rb += 4; op += 4 * (long)ROWF; }

    // prologue: batches 0,1 in flight
    ISSUE(rb,     0)
    ISSUE(rb + 4, 1)

    // warm-up: batches 0..7 (rows h0-30 .. h0+1; last computes ro up to h0-1)
#pragma unroll 1
    for (int p = 0; p < 4; ++p) { SUPER(0, 0, 0, 1, 1) SUPER(4, 1, 0, 1, 1) }

    // emit: batches 8..69 (ro = h0 .. h0+247), all rows unconditionally stored
#pragma unroll 1
    for (int p = 0; p < 31; ++p) { SUPER(0, 0, 1, 1, 1) SUPER(4, 1, 1, 1, 1) }

    // tail: batches 70,71 (ro = h0+248 .. h0+255) — no further issues
    SUPER(0, 0, 1, 1, 0)
    SUPER(4, 1, 1, 0, 0)

#undef SUPER
#undef CPWAIT
#undef MIX
#undef ROWCOMP
#undef ISSUE
}

extern "C" void kernel_launch(void* const* d_in, const int* in_sizes, int n_in,
                              void* d_out, int out_size)
{
    const float* D   = (const float*)d_in[0];   // (4096, 4096, 3) f32
    const float* Cm  = (const float*)d_in[1];   // (3, 3) f32
    float*       out = (float*)d_out;           // (4096, 4096, 3) f32
    dim3 grid(32, 16);                          // 512 blocks, uniform 128-col strips
    chem_kernel<<<grid, TPB>>>(D, Cm, out);
}